// round 1
// baseline (speedup 1.0000x reference)
#include <cuda_runtime.h>
#include <cuda_bf16.h>
#include <math.h>

#define GMM_D 64
#define GMM_K 64
#define TPB   256

#define LOG_2PI 1.8378770664093453f

// Scratch (no cudaMalloc allowed)
__device__ float g_A[GMM_K * GMM_D];   // -0.5 * exp(-logvar)
__device__ float g_B[GMM_K * GMM_D];   // mu * exp(-logvar)
__device__ float g_C[GMM_K];           // per-component constant incl. normalized logprior

typedef unsigned long long ull;

__device__ __forceinline__ ull pack2(float lo, float hi) {
    ull r;
    asm("mov.b64 %0, {%1, %2};" : "=l"(r) : "f"(lo), "f"(hi));
    return r;
}
__device__ __forceinline__ void unpack2(ull v, float& lo, float& hi) {
    asm("mov.b64 {%0, %1}, %2;" : "=f"(lo), "=f"(hi) : "l"(v));
}
__device__ __forceinline__ ull fma2(ull a, ull b, ull c) {
    ull d;
    asm("fma.rn.f32x2 %0, %1, %2, %3;" : "=l"(d) : "l"(a), "l"(b), "l"(c));
    return d;
}
__device__ __forceinline__ ull add2(ull a, ull b) {
    ull d;
    asm("add.rn.f32x2 %0, %1, %2;" : "=l"(d) : "l"(a), "l"(b));
    return d;
}

// ---------------------------------------------------------------------------
// Precompute A' = -0.5*exp(-lv), B = mu*exp(-lv),
// C[k] = -0.5*(sum_d lv + mu^2*exp(-lv)) - 0.5*D*log2pi + (lp[k] - lse(lp))
// ---------------------------------------------------------------------------
__global__ void gmm_pre(const float* __restrict__ mu,
                        const float* __restrict__ lv,
                        const float* __restrict__ lp) {
    __shared__ float s_lse;
    int tid = threadIdx.x;
    if (tid == 0) {
        float m = -INFINITY;
        for (int k = 0; k < GMM_K; k++) m = fmaxf(m, lp[k]);
        float s = 0.f;
        for (int k = 0; k < GMM_K; k++) s += expf(lp[k] - m);
        s_lse = m + logf(s);
    }
    __syncthreads();
    for (int i = tid; i < GMM_K * GMM_D; i += blockDim.x) {
        float l = lv[i];
        float w = expf(-l);
        g_A[i] = -0.5f * w;
        g_B[i] = mu[i] * w;
    }
    if (tid < GMM_K) {
        int k = tid;
        float s = 0.f;
        for (int d = 0; d < GMM_D; d++) {
            float l = lv[k * GMM_D + d];
            float w = expf(-l);
            float m = mu[k * GMM_D + d];
            s += l + m * m * w;
        }
        g_C[k] = -0.5f * s - 0.5f * (float)GMM_D * LOG_2PI + lp[k] - s_lse;
    }
}

// ---------------------------------------------------------------------------
// Main kernel: one sample per thread, f32x2 packed FMA inner loop.
// smem layout (floats): sA[4096] | sB[4096] | sC[64] | sXW[16640]
//   sXW first holds the padded X tile (256 rows x 65), then is reused
//   as the per-thread weighted[k] store (k*256 + tid, max 16384).
// ---------------------------------------------------------------------------
__global__ void __launch_bounds__(TPB, 2)
gmm_main(const float* __restrict__ X, float* __restrict__ out, int N) {
    extern __shared__ float sm[];
    float* sA  = sm;
    float* sB  = sm + GMM_K * GMM_D;
    float* sC  = sm + 2 * GMM_K * GMM_D;
    float* sXW = sm + 2 * GMM_K * GMM_D + GMM_K;

    const int tid = threadIdx.x;
    const int n0  = blockIdx.x * TPB;

    // Stage A', B, C
    #pragma unroll 4
    for (int i = tid; i < GMM_K * GMM_D; i += TPB) {
        sA[i] = g_A[i];
        sB[i] = g_B[i];
    }
    if (tid < GMM_K) sC[tid] = g_C[tid];

    // Stage X tile coalesced, pad rows to 65 floats (conflict-free)
    const float* xg = X + (size_t)n0 * GMM_D;
    #pragma unroll 4
    for (int i = tid; i < TPB * GMM_D; i += TPB) {
        int r = i >> 6;
        int c = i & 63;
        sXW[r * 65 + c] = xg[i];
    }
    __syncthreads();

    // Copy my row into packed f32x2 registers
    ull xp[GMM_D / 2];
    #pragma unroll
    for (int j = 0; j < GMM_D / 2; j++) {
        float lo = sXW[tid * 65 + 2 * j];
        float hi = sXW[tid * 65 + 2 * j + 1];
        xp[j] = pack2(lo, hi);
    }
    __syncthreads();  // everyone done reading sX before it becomes sW

    float maxv = -INFINITY;

    #pragma unroll 4
    for (int k = 0; k < GMM_K; k++) {
        const float4* a4 = reinterpret_cast<const float4*>(sA + k * GMM_D);
        const float4* b4 = reinterpret_cast<const float4*>(sB + k * GMM_D);
        ull acc0 = 0ull, acc1 = 0ull, acc2 = 0ull, acc3 = 0ull;
        #pragma unroll
        for (int j = 0; j < GMM_D / 4; j++) {      // 16 float4 per row
            float4 a = a4[j];
            float4 b = b4[j];
            ull ap0 = pack2(a.x, a.y), ap1 = pack2(a.z, a.w);
            ull bp0 = pack2(b.x, b.y), bp1 = pack2(b.z, b.w);
            // u = B + x*A'  (A' already carries -0.5)
            // acc += x*u  =>  x*B - 0.5*x^2*exp(-lv)... per element
            ull u0 = fma2(xp[2 * j],     ap0, bp0);
            ull u1 = fma2(xp[2 * j + 1], ap1, bp1);
            if (j & 1) {
                acc2 = fma2(xp[2 * j],     u0, acc2);
                acc3 = fma2(xp[2 * j + 1], u1, acc3);
            } else {
                acc0 = fma2(xp[2 * j],     u0, acc0);
                acc1 = fma2(xp[2 * j + 1], u1, acc1);
            }
        }
        acc0 = add2(acc0, acc1);
        acc2 = add2(acc2, acc3);
        acc0 = add2(acc0, acc2);
        float lo, hi;
        unpack2(acc0, lo, hi);
        float w = lo + hi + sC[k];
        sXW[k * TPB + tid] = w;          // weighted[k] for this sample
        maxv = fmaxf(maxv, w);
    }

    // logsumexp over K for this sample
    float ssum = 0.f;
    #pragma unroll 8
    for (int k = 0; k < GMM_K; k++)
        ssum += __expf(sXW[k * TPB + tid] - maxv);
    float lse = maxv + __logf(ssum);

    // write log-posteriors, coalesced per k
    const int n = n0 + tid;
    #pragma unroll 8
    for (int k = 0; k < GMM_K; k++)
        out[(size_t)k * N + n] = sXW[k * TPB + tid] - lse;
}

extern "C" void kernel_launch(void* const* d_in, const int* in_sizes, int n_in,
                              void* d_out, int out_size) {
    const float* X  = (const float*)d_in[0];
    const float* mu = (const float*)d_in[1];
    const float* lv = (const float*)d_in[2];
    const float* lp = (const float*)d_in[3];
    float* out = (float*)d_out;

    const int K = in_sizes[3];            // 64
    const int D = in_sizes[1] / K;        // 64
    const int N = in_sizes[0] / D;        // 131072

    gmm_pre<<<1, 256>>>(mu, lv, lp);

    const int smem_floats = 2 * GMM_K * GMM_D + GMM_K + (TPB * 65);
    const size_t smem = (size_t)smem_floats * sizeof(float);
    cudaFuncSetAttribute(gmm_main, cudaFuncAttributeMaxDynamicSharedMemorySize, (int)smem);
    gmm_main<<<N / TPB, TPB, smem>>>(X, out, N);
}

// round 2
// speedup vs baseline: 1.2070x; 1.2070x over previous
#include <cuda_runtime.h>
#include <cuda_bf16.h>
#include <math.h>

#define GMM_D 64
#define GMM_K 64
#define TPB   128
#define SPT   2                  // samples per thread
#define SPB   (TPB * SPT)        // 256 samples per block

#define LOG_2PI 1.8378770664093453f

// Scratch (no cudaMalloc allowed)
__device__ float g_A[GMM_K * GMM_D];   // -0.5 * exp(-logvar)
__device__ float g_B[GMM_K * GMM_D];   // mu * exp(-logvar)
__device__ float g_C[GMM_K];           // per-component constant incl. normalized logprior

typedef unsigned long long ull;

__device__ __forceinline__ void unpack2(ull v, float& lo, float& hi) {
    asm("mov.b64 {%0, %1}, %2;" : "=f"(lo), "=f"(hi) : "l"(v));
}
__device__ __forceinline__ ull fma2(ull a, ull b, ull c) {
    ull d;
    asm("fma.rn.f32x2 %0, %1, %2, %3;" : "=l"(d) : "l"(a), "l"(b), "l"(c));
    return d;
}
__device__ __forceinline__ ull add2(ull a, ull b) {
    ull d;
    asm("add.rn.f32x2 %0, %1, %2;" : "=l"(d) : "l"(a), "l"(b));
    return d;
}

// ---------------------------------------------------------------------------
// Precompute A' = -0.5*exp(-lv), B = mu*exp(-lv),
// C[k] = -0.5*(sum_d lv + mu^2*exp(-lv)) - 0.5*D*log2pi + (lp[k] - lse(lp))
// ---------------------------------------------------------------------------
__global__ void gmm_pre(const float* __restrict__ mu,
                        const float* __restrict__ lv,
                        const float* __restrict__ lp) {
    __shared__ float s_lse;
    int tid = threadIdx.x;
    if (tid == 0) {
        float m = -INFINITY;
        for (int k = 0; k < GMM_K; k++) m = fmaxf(m, lp[k]);
        float s = 0.f;
        for (int k = 0; k < GMM_K; k++) s += expf(lp[k] - m);
        s_lse = m + logf(s);
    }
    __syncthreads();
    for (int i = tid; i < GMM_K * GMM_D; i += blockDim.x) {
        float l = lv[i];
        float w = expf(-l);
        g_A[i] = -0.5f * w;
        g_B[i] = mu[i] * w;
    }
    if (tid < GMM_K) {
        int k = tid;
        float s = 0.f;
        for (int d = 0; d < GMM_D; d++) {
            float l = lv[k * GMM_D + d];
            float w = expf(-l);
            float m = mu[k * GMM_D + d];
            s += l + m * m * w;
        }
        g_C[k] = -0.5f * s - 0.5f * (float)GMM_D * LOG_2PI + lp[k] - s_lse;
    }
}

// ---------------------------------------------------------------------------
// Main kernel: 2 samples per thread, f32x2 packed FMA inner loop.
// smem (floats): sA[4096] | sB[4096] | sC[64] | sXW[16640]
//   sXW first holds the padded X tile (256 rows x 65 floats), then is reused
//   as the per-sample weighted store w[k][s] (64*256 floats).
// ---------------------------------------------------------------------------
__global__ void __launch_bounds__(TPB, 2)
gmm_main(const float* __restrict__ X, float* __restrict__ out, int N) {
    extern __shared__ float sm[];
    float* sA  = sm;                              // 4096 floats (16B aligned)
    float* sB  = sm + GMM_K * GMM_D;              // 4096 floats
    float* sC  = sm + 2 * GMM_K * GMM_D;          // 64 floats
    float* sXW = sm + 2 * GMM_K * GMM_D + GMM_K;  // 16640 floats (16B aligned)

    const int tid = threadIdx.x;
    const int n0  = blockIdx.x * SPB;

    // Stage A', B, C (coalesced float4)
    {
        const float4* gA4 = (const float4*)g_A;
        const float4* gB4 = (const float4*)g_B;
        float4* sA4 = (float4*)sA;
        float4* sB4 = (float4*)sB;
        #pragma unroll
        for (int i = tid; i < GMM_K * GMM_D / 4; i += TPB) {
            sA4[i] = gA4[i];
            sB4[i] = gB4[i];
        }
        if (tid < GMM_K) sC[tid] = g_C[tid];
    }

    // Stage X tile (256 rows x 64), padded rows of 65 floats
    {
        const float4* xg4 = (const float4*)(X + (size_t)n0 * GMM_D);
        #pragma unroll
        for (int i = tid; i < SPB * GMM_D / 4; i += TPB) {
            float4 v = xg4[i];
            int r = i >> 4;
            int c = (i & 15) << 2;
            float* p = &sXW[r * 65 + c];
            p[0] = v.x; p[1] = v.y; p[2] = v.z; p[3] = v.w;
        }
    }
    __syncthreads();

    // Each thread owns rows tid and tid+TPB -> packed f32x2 registers
    ull x0[GMM_D / 2], x1[GMM_D / 2];
    {
        const ull* r0 = (const ull*)(sXW + tid * 65);           // 65 odd: not 8B-aligned for odd tid? 65*4=260B
        // 260 is 4B-aligned only; do scalar-safe loads via float2 semantics:
        const float* p0 = sXW + tid * 65;
        const float* p1 = sXW + (tid + TPB) * 65;
        #pragma unroll
        for (int j = 0; j < GMM_D / 2; j++) {
            float a = p0[2 * j], b = p0[2 * j + 1];
            float c = p1[2 * j], d = p1[2 * j + 1];
            asm("mov.b64 %0, {%1, %2};" : "=l"(x0[j]) : "f"(a), "f"(b));
            asm("mov.b64 %0, {%1, %2};" : "=l"(x1[j]) : "f"(c), "f"(d));
        }
        (void)r0;
    }
    __syncthreads();   // everyone done reading X tile; sXW becomes w-store

    float max0 = -INFINITY, max1 = -INFINITY;

    #pragma unroll 2
    for (int k = 0; k < GMM_K; k++) {
        const ulonglong2* a2 = (const ulonglong2*)sA + k * (GMM_D / 4);
        const ulonglong2* b2 = (const ulonglong2*)sB + k * (GMM_D / 4);
        ull p00 = 0ull, p01 = 0ull, p10 = 0ull, p11 = 0ull;
        #pragma unroll
        for (int j = 0; j < GMM_D / 4; j++) {      // 16 iterations
            ulonglong2 av = a2[j];                 // (A[4j..4j+1], A[4j+2..4j+3]) packed pairs
            ulonglong2 bv = b2[j];
            // u = B + x*A'   then   acc += x*u   (A' carries the -0.5)
            ull u0 = fma2(x0[2 * j],     av.x, bv.x);
            ull v0 = fma2(x0[2 * j + 1], av.y, bv.y);
            ull u1 = fma2(x1[2 * j],     av.x, bv.x);
            ull v1 = fma2(x1[2 * j + 1], av.y, bv.y);
            p00 = fma2(x0[2 * j],     u0, p00);
            p01 = fma2(x0[2 * j + 1], v0, p01);
            p10 = fma2(x1[2 * j],     u1, p10);
            p11 = fma2(x1[2 * j + 1], v1, p11);
        }
        float ck = sC[k];
        {
            ull s = add2(p00, p01);
            float lo, hi; unpack2(s, lo, hi);
            float w = lo + hi + ck;
            sXW[k * SPB + tid] = w;
            max0 = fmaxf(max0, w);
        }
        {
            ull s = add2(p10, p11);
            float lo, hi; unpack2(s, lo, hi);
            float w = lo + hi + ck;
            sXW[k * SPB + tid + TPB] = w;
            max1 = fmaxf(max1, w);
        }
    }
    __syncwarp();

    // logsumexp over K for both samples
    float s0 = 0.f, s1 = 0.f;
    #pragma unroll 8
    for (int k = 0; k < GMM_K; k++) {
        s0 += __expf(sXW[k * SPB + tid] - max0);
        s1 += __expf(sXW[k * SPB + tid + TPB] - max1);
    }
    const float l0 = max0 + __logf(s0);
    const float l1 = max1 + __logf(s1);

    // write log-posteriors, coalesced per k
    #pragma unroll 8
    for (int k = 0; k < GMM_K; k++) {
        out[(size_t)k * N + n0 + tid]       = sXW[k * SPB + tid] - l0;
        out[(size_t)k * N + n0 + TPB + tid] = sXW[k * SPB + tid + TPB] - l1;
    }
}

extern "C" void kernel_launch(void* const* d_in, const int* in_sizes, int n_in,
                              void* d_out, int out_size) {
    const float* X  = (const float*)d_in[0];
    const float* mu = (const float*)d_in[1];
    const float* lv = (const float*)d_in[2];
    const float* lp = (const float*)d_in[3];
    float* out = (float*)d_out;

    const int K = in_sizes[3];            // 64
    const int D = in_sizes[1] / K;        // 64
    const int N = in_sizes[0] / D;        // 131072

    gmm_pre<<<1, 256>>>(mu, lv, lp);

    const int smem_floats = 2 * GMM_K * GMM_D + GMM_K + (SPB * 65);
    const size_t smem = (size_t)smem_floats * sizeof(float);
    cudaFuncSetAttribute(gmm_main, cudaFuncAttributeMaxDynamicSharedMemorySize, (int)smem);
    gmm_main<<<N / SPB, TPB, smem>>>(X, out, N);
}

// round 3
// speedup vs baseline: 1.3811x; 1.1443x over previous
#include <cuda_runtime.h>
#include <cuda_bf16.h>
#include <math.h>

#define GMM_D 64
#define GMM_K 64
#define BS    128            // samples per block
#define TPB   256
#define NJP   64             // f32x2 pair-steps along j (J=128)
#define XROW  129            // padded sX row stride in ull

#define LOG_2PI 1.8378770664093453f

__device__ float g_A[GMM_K * GMM_D];   // -0.5 * exp(-logvar)
__device__ float g_B[GMM_K * GMM_D];   // mu * exp(-logvar)
__device__ float g_C[GMM_K];           // per-k constant incl. normalized logprior

typedef unsigned long long ull;

__device__ __forceinline__ ull pack2(float lo, float hi) {
    ull r; asm("mov.b64 %0, {%1, %2};" : "=l"(r) : "f"(lo), "f"(hi)); return r;
}
__device__ __forceinline__ void unpack2(ull v, float& lo, float& hi) {
    asm("mov.b64 {%0, %1}, %2;" : "=f"(lo), "=f"(hi) : "l"(v));
}
__device__ __forceinline__ ull fma2(ull a, ull b, ull c) {
    ull d; asm("fma.rn.f32x2 %0, %1, %2, %3;" : "=l"(d) : "l"(a), "l"(b), "l"(c)); return d;
}

// ---------------------------------------------------------------------------
__global__ void gmm_pre(const float* __restrict__ mu,
                        const float* __restrict__ lv,
                        const float* __restrict__ lp) {
    __shared__ float s_lse;
    int tid = threadIdx.x;
    if (tid == 0) {
        float m = -INFINITY;
        for (int k = 0; k < GMM_K; k++) m = fmaxf(m, lp[k]);
        float s = 0.f;
        for (int k = 0; k < GMM_K; k++) s += expf(lp[k] - m);
        s_lse = m + logf(s);
    }
    __syncthreads();
    for (int i = tid; i < GMM_K * GMM_D; i += blockDim.x) {
        float l = lv[i];
        float w = expf(-l);
        g_A[i] = -0.5f * w;
        g_B[i] = mu[i] * w;
    }
    if (tid < GMM_K) {
        int k = tid;
        float s = 0.f;
        for (int d = 0; d < GMM_D; d++) {
            float l = lv[k * GMM_D + d];
            float w = expf(-l);
            float m = mu[k * GMM_D + d];
            s += l + m * m * w;
        }
        g_C[k] = -0.5f * s - 0.5f * (float)GMM_D * LOG_2PI + lp[k] - s_lse;
    }
}

// ---------------------------------------------------------------------------
// Register-tiled GEMM: weighted[n,k] = sum_j X'[n,j] * W[k,j] + C[k]
//   X'[n, j<64] = x[n,j],  X'[n, 64+j] = x[n,j]^2
//   W[k, j<64]  = B[k,j],  W[k, 64+j]  = A'[k,j]
// Block: 128 samples x 64 k.  Thread (ts=tid&15, tk=tid>>4): 8 samples x 4 k.
// smem (bytes):
//   sX : ull[64][129]  = 66048   (pairs along j, sample-major rows; reused by epilogue)
//   sW : ull[64][64]   = 32768
//   sC : float[64]     = 256
// ---------------------------------------------------------------------------
__global__ void __launch_bounds__(TPB, 2)
gmm_main(const float* __restrict__ X, float* __restrict__ out, int N) {
    extern __shared__ char smraw[];
    ull*   sX = (ull*)smraw;                         // 64 * 129
    ull*   sW = sX + NJP * XROW;                     // 64 * 64
    float* sC = (float*)(sW + GMM_K * NJP);          // 64

    const int tid = threadIdx.x;
    const int ts  = tid & 15;
    const int tk  = tid >> 4;
    const int n0  = blockIdx.x * BS;

    // ---- stage W (packed f32x2 pairs along j) ----
    {
        const float2* gB2 = (const float2*)g_B;
        const float2* gA2 = (const float2*)g_A;
        #pragma unroll
        for (int idx = tid; idx < GMM_K * 32; idx += TPB) {
            int k  = idx >> 5;
            int jq = idx & 31;
            float2 b = gB2[k * 32 + jq];
            float2 a = gA2[k * 32 + jq];
            sW[k * NJP + jq]      = pack2(b.x, b.y);
            sW[k * NJP + 32 + jq] = pack2(a.x, a.y);
        }
        if (tid < GMM_K) sC[tid] = g_C[tid];
    }

    // ---- stage X' (coalesced float2 global reads) ----
    {
        const float2* xg2 = (const float2*)(X + (size_t)n0 * GMM_D);
        #pragma unroll
        for (int i = 0; i < 16; i++) {
            int idx = tid + TPB * i;      // < 128*32
            int n   = idx >> 5;
            int dp  = idx & 31;
            float2 v = xg2[n * 32 + dp];
            sX[dp * XROW + n]        = pack2(v.x, v.y);
            sX[(32 + dp) * XROW + n] = pack2(v.x * v.x, v.y * v.y);
        }
    }
    __syncthreads();

    // ---- main GEMM loop ----
    ull acc[8][4];
    #pragma unroll
    for (int i = 0; i < 8; i++)
        #pragma unroll
        for (int kk = 0; kk < 4; kk++) acc[i][kk] = 0ull;

    const ull* wbase = sW + tk * 4 * NJP;
    const ull* xbase = sX + ts;

    #pragma unroll 4
    for (int jp = 0; jp < NJP; jp++) {
        ull wv[4];
        #pragma unroll
        for (int kk = 0; kk < 4; kk++) wv[kk] = wbase[kk * NJP + jp];
        ull xv[8];
        #pragma unroll
        for (int i = 0; i < 8; i++) xv[i] = xbase[jp * XROW + 16 * i];
        #pragma unroll
        for (int i = 0; i < 8; i++)
            #pragma unroll
            for (int kk = 0; kk < 4; kk++)
                acc[i][kk] = fma2(xv[i], wv[kk], acc[i][kk]);
    }

    // ---- finalize weighted values ----
    float w[8][4];
    #pragma unroll
    for (int kk = 0; kk < 4; kk++) {
        float ck = sC[tk * 4 + kk];
        #pragma unroll
        for (int i = 0; i < 8; i++) {
            float lo, hi; unpack2(acc[i][kk], lo, hi);
            w[i][kk] = lo + hi + ck;
        }
    }
    __syncthreads();   // sX no longer needed; reuse as reduction scratch

    float* sR = (float*)sX;          // [16][128] partials
    float* sM = sR + 16 * BS;        // [128] per-sample max -> lse

    // ---- per-sample max over k (two-stage) ----
    #pragma unroll
    for (int i = 0; i < 8; i++) {
        float m = fmaxf(fmaxf(w[i][0], w[i][1]), fmaxf(w[i][2], w[i][3]));
        sR[tk * BS + ts + 16 * i] = m;
    }
    __syncthreads();
    if (tid < BS) {
        float m = -INFINITY;
        #pragma unroll
        for (int p = 0; p < 16; p++) m = fmaxf(m, sR[p * BS + tid]);
        sM[tid] = m;
    }
    __syncthreads();

    // ---- per-sample sum of exp (two-stage) ----
    #pragma unroll
    for (int i = 0; i < 8; i++) {
        float m = sM[ts + 16 * i];
        float s = __expf(w[i][0] - m) + __expf(w[i][1] - m)
                + __expf(w[i][2] - m) + __expf(w[i][3] - m);
        sR[tk * BS + ts + 16 * i] = s;
    }
    __syncthreads();
    if (tid < BS) {
        float s = 0.f;
        #pragma unroll
        for (int p = 0; p < 16; p++) s += sR[p * BS + tid];
        sM[tid] = sM[tid] + __logf(s);   // lse
    }
    __syncthreads();

    // ---- write log-posteriors ----
    #pragma unroll
    for (int kk = 0; kk < 4; kk++) {
        float* ob = out + (size_t)(tk * 4 + kk) * N + n0 + ts;
        #pragma unroll
        for (int i = 0; i < 8; i++)
            ob[16 * i] = w[i][kk] - sM[ts + 16 * i];
    }
}

extern "C" void kernel_launch(void* const* d_in, const int* in_sizes, int n_in,
                              void* d_out, int out_size) {
    const float* X  = (const float*)d_in[0];
    const float* mu = (const float*)d_in[1];
    const float* lv = (const float*)d_in[2];
    const float* lp = (const float*)d_in[3];
    float* out = (float*)d_out;

    const int K = in_sizes[3];            // 64
    const int D = in_sizes[1] / K;        // 64
    const int N = in_sizes[0] / D;        // 131072

    gmm_pre<<<1, 256>>>(mu, lv, lp);

    const size_t smem = (size_t)(NJP * XROW + GMM_K * NJP) * sizeof(ull)
                      + GMM_K * sizeof(float);
    cudaFuncSetAttribute(gmm_main, cudaFuncAttributeMaxDynamicSharedMemorySize, (int)smem);
    gmm_main<<<N / BS, TPB, smem>>>(X, out, N);
}

// round 4
// speedup vs baseline: 1.4062x; 1.0182x over previous
#include <cuda_runtime.h>
#include <cuda_bf16.h>
#include <math.h>

#define GMM_D 64
#define GMM_K 64
#define BS    128           // samples per block
#define TPB   128
#define NJ2   32            // ulonglong2 steps along j (J=128 floats = 64 pairs = 32 ull2)
#define RSX   129           // sX row stride (ulonglong2 units)
#define RSW   65            // sW row stride (ulonglong2 units)
#define RSO   132           // sO row stride (floats)

typedef unsigned long long ull;

__device__ __forceinline__ ull pack2(float lo, float hi) {
    ull r; asm("mov.b64 %0, {%1, %2};" : "=l"(r) : "f"(lo), "f"(hi)); return r;
}
__device__ __forceinline__ void unpack2(ull v, float& lo, float& hi) {
    asm("mov.b64 {%0, %1}, %2;" : "=f"(lo), "=f"(hi) : "l"(v));
}
__device__ __forceinline__ ull fma2(ull a, ull b, ull c) {
    ull d; asm("fma.rn.f32x2 %0, %1, %2, %3;" : "=l"(d) : "l"(a), "l"(b), "l"(c)); return d;
}

// ---------------------------------------------------------------------------
// Fused GMM posterior kernel.
// GEMM view: weighted[n,k] = sum_j X'[n,j]*W[k,j] + C[k]
//   X'[n,j<64] = x[n,j], X'[n,64+j] = x[n,j]^2
//   W[k,j<64]  = mu*e^{-lv}, W[k,64+j] = -0.5*e^{-lv}
//   C[k] = -0.5*sum_d(lv + mu^2 e^{-lv}) + lp[k]
// (constants uniform over k cancel in the posterior normalization)
// Block: 128 samples x 64 k. Warp: 32 samples x 64 k. Thread: 8 x 8.
// Lanes: sg = lane&3 (sample group), klane = lane>>2 (k group).
//   thread samples: warp*32 + sg + 4m   (m=0..7)
//   thread k's:     kk*8 + klane        (kk=0..7)
// smem: sX ull2[32][129] (66048 B) | sW ull2[32][65] (33280 B) | sC f[64] | sLse f[128]
//   sO f[64][132] overlays sX after the main loop.
// ---------------------------------------------------------------------------
__global__ void __launch_bounds__(TPB, 2)
gmm_fused(const float* __restrict__ X, const float* __restrict__ mu,
          const float* __restrict__ lv, const float* __restrict__ lp,
          float* __restrict__ out, int N) {
    extern __shared__ char smraw[];
    ulonglong2* sX  = (ulonglong2*)smraw;                 // 32 * 129
    ulonglong2* sW  = sX + NJ2 * RSX;                     // 32 * 65
    float*      sC  = (float*)(sW + NJ2 * RSW);           // 64
    float*      sLse= sC + GMM_K;                         // 128
    float*      sO  = (float*)smraw;                      // overlay: 64 * 132

    const int t  = threadIdx.x;
    const int n0 = blockIdx.x * BS;

    // ---- stage W: jp-major, 2 j-pairs per ulonglong2 ----
    const float4* mu4 = (const float4*)mu;
    const float4* lv4 = (const float4*)lv;
    #pragma unroll
    for (int i = 0; i < 8; i++) {
        int idx = i * TPB + t;            // 0..1023
        int k   = idx >> 4;
        int d4  = idx & 15;
        float4 m = mu4[k * 16 + d4];
        float4 l = lv4[k * 16 + d4];
        float w0 = __expf(-l.x), w1 = __expf(-l.y);
        float w2 = __expf(-l.z), w3 = __expf(-l.w);
        ulonglong2 B, A;
        B.x = pack2(m.x * w0, m.y * w1);  B.y = pack2(m.z * w2, m.w * w3);
        A.x = pack2(-0.5f * w0, -0.5f * w1); A.y = pack2(-0.5f * w2, -0.5f * w3);
        sW[d4 * RSW + k]        = B;      // j-block 0..63  -> rows 0..15
        sW[(d4 + 16) * RSW + k] = A;      // j-block 64..127 -> rows 16..31
    }

    // ---- stage X': x and x^2, jp-major ----
    const float4* xg4 = (const float4*)(X + (size_t)n0 * GMM_D);
    #pragma unroll
    for (int i = 0; i < 16; i++) {
        int idx = i * TPB + t;            // 0..2047
        int n   = idx >> 4;
        int d4  = idx & 15;
        float4 v = xg4[idx];
        ulonglong2 xa, xs;
        xa.x = pack2(v.x, v.y);            xa.y = pack2(v.z, v.w);
        xs.x = pack2(v.x * v.x, v.y * v.y); xs.y = pack2(v.z * v.z, v.w * v.w);
        sX[d4 * RSX + n]        = xa;
        sX[(d4 + 16) * RSX + n] = xs;
    }

    // ---- per-k constant (deterministic, no atomics) ----
    if (t < GMM_K) {
        int k = t;
        float s = 0.f;
        #pragma unroll 4
        for (int d4 = 0; d4 < 16; d4++) {
            float4 l = lv4[k * 16 + d4];
            float4 m = mu4[k * 16 + d4];
            s += l.x + m.x * m.x * __expf(-l.x);
            s += l.y + m.y * m.y * __expf(-l.y);
            s += l.z + m.z * m.z * __expf(-l.z);
            s += l.w + m.w * m.w * __expf(-l.w);
        }
        sC[k] = -0.5f * s + lp[k];
    }
    __syncthreads();

    // ---- main GEMM loop: thread tile 8 samples x 8 k ----
    const int lane   = t & 31;
    const int warp   = t >> 5;
    const int sg     = lane & 3;
    const int klane  = lane >> 2;
    const int s_base = warp * 32 + sg;

    ull acc[8][8];
    #pragma unroll
    for (int m = 0; m < 8; m++)
        #pragma unroll
        for (int kk = 0; kk < 8; kk++) acc[m][kk] = 0ull;

    const ulonglong2* xb = sX + s_base;
    const ulonglong2* wb = sW + klane;

    #pragma unroll 2
    for (int jp2 = 0; jp2 < NJ2; jp2++) {
        ulonglong2 wv[8], xv[8];
        #pragma unroll
        for (int kk = 0; kk < 8; kk++) wv[kk] = wb[jp2 * RSW + kk * 8];
        #pragma unroll
        for (int m = 0; m < 8; m++)    xv[m]  = xb[jp2 * RSX + 4 * m];
        #pragma unroll
        for (int m = 0; m < 8; m++)
            #pragma unroll
            for (int kk = 0; kk < 8; kk++) {
                acc[m][kk] = fma2(xv[m].x, wv[kk].x, acc[m][kk]);
                acc[m][kk] = fma2(xv[m].y, wv[kk].y, acc[m][kk]);
            }
    }

    __syncthreads();   // sX dead; becomes sO

    // ---- scatter weighted values to sO[k][sample] (conflict-free, stride 132) ----
    #pragma unroll
    for (int kk = 0; kk < 8; kk++) {
        int k = kk * 8 + klane;
        float ck = sC[k];
        #pragma unroll
        for (int m = 0; m < 8; m++) {
            float lo, hi; unpack2(acc[m][kk], lo, hi);
            sO[k * RSO + s_base + 4 * m] = lo + hi + ck;
        }
    }
    __syncthreads();

    // ---- per-sample logsumexp over k ----
    {
        float mx = -INFINITY;
        #pragma unroll 8
        for (int k = 0; k < GMM_K; k++) mx = fmaxf(mx, sO[k * RSO + t]);
        float s = 0.f;
        #pragma unroll 8
        for (int k = 0; k < GMM_K; k++) s += __expf(sO[k * RSO + t] - mx);
        sLse[t] = mx + __logf(s);
    }
    __syncthreads();

    // ---- coalesced float4 writeout: 4 k-rows at a time ----
    {
        const int kq = t >> 5;            // 0..3
        float4 L = ((const float4*)sLse)[lane];
        #pragma unroll
        for (int i = 0; i < 16; i++) {
            int k = i * 4 + kq;
            float4 v = *(const float4*)&sO[k * RSO + lane * 4];
            float4 r;
            r.x = v.x - L.x; r.y = v.y - L.y; r.z = v.z - L.z; r.w = v.w - L.w;
            *(float4*)(out + (size_t)k * N + n0 + lane * 4) = r;
        }
    }
}

extern "C" void kernel_launch(void* const* d_in, const int* in_sizes, int n_in,
                              void* d_out, int out_size) {
    const float* X  = (const float*)d_in[0];
    const float* mu = (const float*)d_in[1];
    const float* lv = (const float*)d_in[2];
    const float* lp = (const float*)d_in[3];
    float* out = (float*)d_out;

    const int K = in_sizes[3];            // 64
    const int D = in_sizes[1] / K;        // 64
    const int N = in_sizes[0] / D;        // 131072

    const size_t smem = (size_t)(NJ2 * RSX + NJ2 * RSW) * sizeof(ulonglong2)
                      + (GMM_K + BS) * sizeof(float);
    cudaFuncSetAttribute(gmm_fused, cudaFuncAttributeMaxDynamicSharedMemorySize, (int)smem);
    gmm_fused<<<N / BS, TPB, smem>>>(X, mu, lv, lp, out, N);
}